// round 17
// baseline (speedup 1.0000x reference)
#include <cuda_runtime.h>
#include <math.h>

// FFT size N = 2^25 = FA * FB * FC, position n = a + FA*b + AB*c
#define LN   25
#define NF   (1 << LN)
#define LA   11
#define FA   (1 << LA)          // 2048
#define LB   7
#define FB   (1 << LB)          // 128
#define LC   7
#define FC   (1 << LC)          // 128
#define AB   (FA * FB)          // 262144
#define GT   32                 // tile width (consecutive fast-dim elements)
#define NTHR 256

#define MTOT (1 << 24)          // problem size B*N = 2^24
#define NBLK (AB / GT)          // 8192 blocks for K1/K5

// XOR swizzle for k3 smem: flips element bits [1:4) from bits [4:7).
// Bijective, preserves 2-element (16B) alignment -> float4-safe.
#define SW(p) ((p) ^ ((((p) >> 4) & 7) << 1))

// 256 MB spectral work buffer + twiddle tables + partials (no runtime allocation)
__device__ float2 g_Z[NF];
__device__ float2 g_W16384[16384];  // W_16384^m (full)
__device__ float2 g_W2048[2048];    // W_2048^m  (full)
__device__ float2 g_W128[128];      // W_128^m   (full)
__device__ float2 g_Wlo[4096];      // W_N^j,        j < 4096
__device__ float2 g_Whi[8192];      // W_N^{4096 j}, j < 8192
__device__ double g_data[NBLK];
__device__ double g_phys[NBLK];

__device__ __forceinline__ float2 cadd(float2 a, float2 b) { return make_float2(a.x + b.x, a.y + b.y); }
__device__ __forceinline__ float2 csub(float2 a, float2 b) { return make_float2(a.x - b.x, a.y - b.y); }
__device__ __forceinline__ float2 cmul(float2 a, float2 b) {
    return make_float2(fmaf(a.x, b.x, -a.y * b.y), fmaf(a.x, b.y, a.y * b.x));
}
// multiply by -i (sgn=+1, forward) or +i (sgn=-1, inverse)
__device__ __forceinline__ float2 crot(float2 a, float sgn) { return make_float2(sgn * a.y, -sgn * a.x); }

// 8-point DFT in registers, natural-order outputs. sgn=+1 fwd, -1 inverse (unnormalized).
__device__ __forceinline__ void dft8(float2* u, float sgn) {
    const float C = 0.70710678118654752440f;
    float2 t0 = cadd(u[0], u[4]), t1 = cadd(u[1], u[5]);
    float2 t2 = cadd(u[2], u[6]), t3 = cadd(u[3], u[7]);
    float2 m4 = csub(u[0], u[4]), m5 = csub(u[1], u[5]);
    float2 m6 = csub(u[2], u[6]), m7 = csub(u[3], u[7]);
    float2 t4 = m4;
    float2 t5 = cmul(m5, make_float2(C, -sgn * C));    // W8^1
    float2 t6 = crot(m6, sgn);                         // W8^2
    float2 t7 = cmul(m7, make_float2(-C, -sgn * C));   // W8^3
    float2 s0 = cadd(t0, t2), s2 = csub(t0, t2);
    float2 s1 = cadd(t1, t3), s3 = crot(csub(t1, t3), sgn);
    float2 r0 = cadd(t4, t6), r2 = csub(t4, t6);
    float2 r1 = cadd(t5, t7), r3 = crot(csub(t5, t7), sgn);
    u[0] = cadd(s0, s1); u[4] = csub(s0, s1);
    u[2] = cadd(s2, s3); u[6] = csub(s2, s3);
    u[1] = cadd(r0, r1); u[5] = csub(r0, r1);
    u[3] = cadd(r2, r3); u[7] = csub(r2, r3);
}

// 8-point DFT with inputs 4..7 known to be zero (k1 zero-padding). In: u[0..3]; out: u[0..7].
__device__ __forceinline__ void dft8h(float2* u, float sgn) {
    const float C = 0.70710678118654752440f;
    float2 t0 = u[0], t1 = u[1], t2 = u[2], t3 = u[3];
    float2 t4 = u[0];
    float2 t5 = cmul(u[1], make_float2(C, -sgn * C));
    float2 t6 = crot(u[2], sgn);
    float2 t7 = cmul(u[3], make_float2(-C, -sgn * C));
    float2 s0 = cadd(t0, t2), s2 = csub(t0, t2);
    float2 s1 = cadd(t1, t3), s3 = crot(csub(t1, t3), sgn);
    float2 r0 = cadd(t4, t6), r2 = csub(t4, t6);
    float2 r1 = cadd(t5, t7), r3 = crot(csub(t5, t7), sgn);
    u[0] = cadd(s0, s1); u[4] = csub(s0, s1);
    u[2] = cadd(s2, s3); u[6] = csub(s2, s3);
    u[1] = cadd(r0, r1); u[5] = csub(r0, r1);
    u[3] = cadd(r2, r3); u[7] = csub(r2, r3);
}

// 4-point DFT in registers, natural order.
__device__ __forceinline__ void dft4(float2* u, float sgn) {
    float2 a0 = cadd(u[0], u[2]), b0 = csub(u[0], u[2]);
    float2 a1 = cadd(u[1], u[3]), b1 = crot(csub(u[1], u[3]), sgn);
    u[0] = cadd(a0, a1); u[2] = csub(a0, a1);
    u[1] = cadd(b0, b1); u[3] = csub(b0, b1);
}

// apply w1^k (k=1..7) to u[1..7], log-depth power tree (depth 3 vs serial 6)
__device__ __forceinline__ void twiddle_chain8(float2* u, float2 w1) {
    float2 w2 = cmul(w1, w1);
    float2 w3 = cmul(w2, w1);
    float2 w4 = cmul(w2, w2);
    float2 w5 = cmul(w4, w1);
    float2 w6 = cmul(w3, w3);
    float2 w7 = cmul(w4, w3);
    u[1] = cmul(u[1], w1); u[2] = cmul(u[2], w2); u[3] = cmul(u[3], w3);
    u[4] = cmul(u[4], w4); u[5] = cmul(u[5], w5); u[6] = cmul(u[6], w6);
    u[7] = cmul(u[7], w7);
}

// digit-reversal maps
// 128 = 8*8*2 DIF: position p -> natural frequency
__device__ __forceinline__ int f128(int p) {
    return (p >> 4) + (((p >> 1) & 7) << 3) + ((p & 1) << 6);
}
// 2048 = 8*8*8*4 DIF: natural frequency k -> scrambled position
__device__ __forceinline__ int pos2048(int k) {
    return ((k & 7) << 8) + (((k >> 3) & 7) << 5) + (((k >> 6) & 7) << 2) + (k >> 9);
}

// ---------------------------------------------------------------- twiddle init
__global__ void k_tw() {
    int idx = blockIdx.x * 128 + threadIdx.x;   // 128 blocks * 128 = 16384
    const double P2 = 6.283185307179586476925286766559;
    if (idx < 16384) { double a = -P2 * idx / 16384.0;    g_W16384[idx] = make_float2((float)cos(a), (float)sin(a)); }
    if (idx < 8192)  { double a = -P2 * idx / 8192.0;     g_Whi[idx]    = make_float2((float)cos(a), (float)sin(a)); }
    if (idx < 4096)  { double a = -P2 * idx / (double)NF; g_Wlo[idx]    = make_float2((float)cos(a), (float)sin(a)); }
    if (idx < 2048)  { double a = -P2 * idx / 2048.0;     g_W2048[idx]  = make_float2((float)cos(a), (float)sin(a)); }
    if (idx < 128)   { double a = -P2 * idx / 128.0;      g_W128[idx]   = make_float2((float)cos(a), (float)sin(a)); }
}

// ------------------------------------- K1: pack Z = du + i*b, FFT over c, data loss
// FUSED pack + stage-1: stage-1's input rows (c = j+16k, k<4) cover [0,64)
// exactly once, and lane index g is row-contiguous -> load directly from
// global (coalesced), compute du / fp32-exact weights / data loss in
// registers, dft8h, STS. Eliminates the pack STS pass + stage-1 LDS pass.
// Stage 2 writes directly to global (register->STG, coalesced per warp).
__global__ __launch_bounds__(NTHR)
void k1_pack_fft(const float* __restrict__ up, const float* __restrict__ utr) {
    __shared__ float2 tile[FC][GT + 1];
    __shared__ double red[NTHR];
    const int t   = threadIdx.x;
    const int ab0 = blockIdx.x * GT;

    float acc = 0.f;
#pragma unroll
    for (int q = t; q < 512; q += NTHR) {
        int g = q & 31, j = q >> 5;
        float2 u[8];
#pragma unroll
        for (int k = 0; k < 4; k++) {
            int n = ab0 + g + AB * (j + (k << 4));   // c = j+16k < 64 -> n < MTOT
            float un = up[n];
            float ud = un - utr[n];
            acc = fmaf(ud, ud, acc);
            float du = 0.f, bw = 0.f;
            if (n < MTOT - 1) {
                du = up[n + 1] - un;
                // EXACT replica of the reference fp32 weights (incl. cancellation noise)
                bw = __fsqrt_rn((float)(n + 1)) - __fsqrt_rn((float)n);
            }
            u[k] = make_float2(du, bw);
        }
        dft8h(u, 1.f);
        twiddle_chain8(u, g_W128[j]);
#pragma unroll
        for (int k = 0; k < 8; k++) tile[j + (k << 4)][g] = u[k];
    }
    __syncthreads();

    // stage 2 in registers + DIRECT global store (digit-reversal in slab index)
    {
        int g = t & 31, m = t >> 5;
        int base = m << 4;
        float2 e0[8], e1[8];
#pragma unroll
        for (int k = 0; k < 8; k++) {
            e0[k] = tile[base + (k << 1)][g];
            e1[k] = tile[base + (k << 1) + 1][g];
        }
        dft8(e0, 1.f); dft8(e1, 1.f);
#pragma unroll
        for (int k = 1; k < 8; k++) e1[k] = cmul(e1[k], g_W128[k << 3]);   // W16^k
#pragma unroll
        for (int k = 0; k < 8; k++) {
            int p0 = base + (k << 1), p1 = p0 + 1;
            g_Z[ab0 + g + AB * f128(p0)] = cadd(e0[k], e1[k]);
            g_Z[ab0 + g + AB * f128(p1)] = csub(e0[k], e1[k]);
        }
    }

    red[t] = (double)acc;
    __syncthreads();
    for (int s = NTHR / 2; s > 0; s >>= 1) { if (t < s) red[t] += red[t + s]; __syncthreads(); }
    if (t == 0) g_data[blockIdx.x] = red[0];
}

// ---------------------- K2/K4: FFT over b (stride FA), twiddle W_16384^{b c'}
// Stage 1: PREFETCH all 16 global loads (both j-halves), then compute; the
// forward pre-twiddle W16384[(j+16k)c'] is a geometric chain with uniform step
// W16384[16c']. Stage 2 stores DIRECTLY to global; inverse post-twiddle chains
// with uniform step W16384[8c'] (f128 of even/odd positions linear in k).
// Inverse (FWD=0) runs c' in [0,64] only (c'-Hermitian symmetry, conv real).
template<int FWD>
__global__ __launch_bounds__(NTHR)
void k2_fftb() {
    __shared__ float2 tile[FB][GT + 1];
    const int t  = threadIdx.x;
    const int cp = blockIdx.x >> 6;             // c' ; FA/GT = 64
    const int a0 = (blockIdx.x & 63) * GT;
    const float sgn = FWD ? 1.f : -1.f;
    const int g  = t & 31;
    const int j0 = t >> 5;                      // j0 in [0,8), second half j0+8

    // ---- stage 1: prefetch 16 loads, then two butterflies ----
    {
        float2 v0[8], v1[8];
#pragma unroll
        for (int k = 0; k < 8; k++) v0[k] = g_Z[a0 + g + FA * (j0 + (k << 4)) + AB * cp];
#pragma unroll
        for (int k = 0; k < 8; k++) v1[k] = g_Z[a0 + g + FA * (j0 + 8 + (k << 4)) + AB * cp];

        if (FWD) {
            // pre-twiddle chain: W16384[(j+16k)cp] = W16384[j*cp] * W16384[16cp]^k
            float2 wk = g_W16384[cp << 4];      // uniform step
            float2 w = g_W16384[j0 * cp];
            v0[0] = cmul(v0[0], w);
#pragma unroll
            for (int k = 1; k < 8; k++) { w = cmul(w, wk); v0[k] = cmul(v0[k], w); }
            w = g_W16384[(j0 + 8) * cp];
            v1[0] = cmul(v1[0], w);
#pragma unroll
            for (int k = 1; k < 8; k++) { w = cmul(w, wk); v1[k] = cmul(v1[k], w); }
        }

        dft8(v0, sgn);
        { float2 w1 = g_W128[j0]; w1.y *= sgn; twiddle_chain8(v0, w1); }
#pragma unroll
        for (int k = 0; k < 8; k++) tile[j0 + (k << 4)][g] = v0[k];

        dft8(v1, sgn);
        { float2 w1 = g_W128[j0 + 8]; w1.y *= sgn; twiddle_chain8(v1, w1); }
#pragma unroll
        for (int k = 0; k < 8; k++) tile[j0 + 8 + (k << 4)][g] = v1[k];
    }
    __syncthreads();

    // ---- stage 2: smem -> registers -> 16-pt -> DIRECT global store ----
    {
        int m = t >> 5;
        int base = m << 4;
        float2 e0[8], e1[8];
#pragma unroll
        for (int k = 0; k < 8; k++) {
            e0[k] = tile[base + (k << 1)][g];
            e1[k] = tile[base + (k << 1) + 1][g];
        }
        dft8(e0, sgn); dft8(e1, sgn);
#pragma unroll
        for (int k = 1; k < 8; k++) {
            float2 w = g_W128[k << 3]; w.y *= sgn;        // W16^k
            e1[k] = cmul(e1[k], w);
        }
        if (FWD) {
#pragma unroll
            for (int k = 0; k < 8; k++) {
                int p0 = base + (k << 1), p1 = p0 + 1;
                g_Z[a0 + g + FA * f128(p0) + AB * cp] = cadd(e0[k], e1[k]);
                g_Z[a0 + g + FA * f128(p1) + AB * cp] = csub(e0[k], e1[k]);
            }
        } else {
            // post-twiddle chain: bb0 = m+8k, bb1 = m+8k+64 -> uniform step W16384[8cp]
            float2 w8 = g_W16384[cp << 3]; w8.y = -w8.y;
            float2 wa = g_W16384[m * cp];        wa.y = -wa.y;
            float2 wb = g_W16384[(m + 64) * cp]; wb.y = -wb.y;
#pragma unroll
            for (int k = 0; k < 8; k++) {
                int bb0 = m + (k << 3), bb1 = bb0 + 64;
                float2 v0 = cmul(cadd(e0[k], e1[k]), wa);
                float2 v1 = cmul(csub(e0[k], e1[k]), wb);
                g_Z[a0 + g + FA * bb0 + AB * cp] = v0;
                g_Z[a0 + g + FA * bb1 + AB * cp] = v1;
                wa = cmul(wa, w8);
                wb = cmul(wb, w8);
            }
        }
    }
}

// -------- K3 stage helpers: 2048 = 8*8*8*4, XOR-swizzled smem layout SW()
__device__ __forceinline__ void k3_r8(float2 (*sm)[FA], int nrow, int t,
                                      int ls, int tmul, int inv) {
    const int s   = 1 << ls;
    const int tot = nrow << 8;      // 256 butterflies per row
    for (int q = t; q < tot; q += NTHR) {
        int row = q >> 8, qq = q & 255;
        int j = qq & (s - 1), m = qq >> ls;
        int base = (m << (ls + 3)) + j;
        float2 u[8];
#pragma unroll
        for (int k = 0; k < 8; k++) u[k] = sm[row][SW(base + (k << ls))];
        float2 w1 = g_W2048[tmul * j];          // single coalesced twiddle load
        if (!inv) {
            dft8(u, 1.f);
            twiddle_chain8(u, w1);
        } else {
            // DIT inverse: conj twiddle BEFORE inverse DFT8
            w1.y = -w1.y;
            twiddle_chain8(u, w1);
            dft8(u, -1.f);
        }
#pragma unroll
        for (int k = 0; k < 8; k++) sm[row][SW(base + (k << ls))] = u[k];
    }
    __syncthreads();
}

// radix-4 span-1 (kept for the h==0 block's unfused path)
__device__ __forceinline__ void k3_r4(float2 (*sm)[FA], int nrow, int t, float sgn) {
    const int tot = nrow << 9;      // 512 quads per row
    for (int q = t; q < tot; q += NTHR) {
        int row = q >> 9, b = (q & 511) << 2;
        float2* rowp = sm[row];
        float4 lo = *reinterpret_cast<const float4*>(&rowp[SW(b)]);
        float4 hi = *reinterpret_cast<const float4*>(&rowp[SW(b + 2)]);
        float2 u[4] = { make_float2(lo.x, lo.y), make_float2(lo.z, lo.w),
                        make_float2(hi.x, hi.y), make_float2(hi.z, hi.w) };
        dft4(u, sgn);
        *reinterpret_cast<float4*>(&rowp[SW(b)])     = make_float4(u[0].x, u[0].y, u[1].x, u[1].y);
        *reinterpret_cast<float4*>(&rowp[SW(b + 2)]) = make_float4(u[2].x, u[2].y, u[3].x, u[3].y);
    }
    __syncthreads();
}

__device__ __forceinline__ float2 herm_P(float2 z1, float2 z2) {
    // DU = (z1 + conj z2)/2 ; B = -i/2 * (z1 - conj z2) ; P = DU*B
    float2 du = make_float2(0.5f * (z1.x + z2.x), 0.5f * (z1.y - z2.y));
    float2 bv = make_float2(0.5f * (z1.y + z2.y), -0.5f * (z1.x - z2.x));
    return cmul(du, bv);
}

// -------- K3: fwd DIF over a (+twiddle), pointwise in scrambled domain, inverse DIT
// Compact grid: 8193 blocks, every block active (pair enumerated in closed form).
// Pairing identity: pos2048(2047 - f) == 2047 - pos2048(f)  (all digits complement)
// -> partner of POSITION p is 2047 - p; quad w pairs with quad 511 - w, elem e <-> 3-e.
// Fused endpoints: the span-256 FFT stages are merged with the global
// load+pre-twiddle (forward) and post-twiddle+store (inverse) — per butterfly
// the 8 touched elements are 8 fully-coalesced 256B global rows per warp.
// Middle (r4 fwd + pairing + r4 inv) fused in registers except idx==0.
// Output chunks with c' > 64 are dead downstream -> skip row1 inverse + store.
__global__ __launch_bounds__(NTHR)
void k3_core() {
    __shared__ __align__(16) float2 sm[2][FA];   // 32 KB, XOR-swizzled
    const int t   = threadIdx.x;
    const int idx = blockIdx.x;
    int b1, c1;
    if (idx < 65)       { c1 = 0;  b1 = idx; }
    else if (idx < 129) { c1 = 64; b1 = idx - 65; }
    else                { int r = idx - 129; c1 = 1 + (r >> 7); b1 = r & 127; }
    const int h1 = b1 + (c1 << LB);
    int h2;
    if (c1 > 0)      h2 = (FB - 1 - b1) + ((FC - c1) << LB);
    else if (b1 > 0) h2 = FB - b1;
    else             h2 = 0;
    const bool self = (h1 == h2);
    const int  nrow = self ? 1 : 2;
    const int  b2 = h2 & (FB - 1), c2 = h2 >> LB;
    const int  hk1 = c1 + FC * b1;             // frequency weight c' + FC*b'
    const int  hk2 = c2 + FC * b2;
    const bool keep1 = (c2 <= 64);             // row1 consumed downstream?
    const int  nrow_inv = keep1 ? nrow : 1;    // rows needing inverse transform

    // FUSED fwd stage 1 (span 256): global load + pre-twiddle W_N^{a*hk} + dft8 + STS.
    // Elements a = j + k*256; lanes have consecutive j -> 8 coalesced 256B rows/warp.
    for (int q = t; q < (nrow << 8); q += NTHR) {
        int row = q >> 8, j = q & 255;
        const int chunk = row ? h2 : h1;
        const int hk    = row ? hk2 : hk1;
        float2 u[8];
#pragma unroll
        for (int k = 0; k < 8; k++) {
            int a = j + (k << 8);
            int e = a * hk;                               // < 2^25, no mod needed
            float2 w = cmul(g_Whi[e >> 12], g_Wlo[e & 4095]);
            u[k] = cmul(g_Z[chunk * FA + a], w);
        }
        dft8(u, 1.f);
        twiddle_chain8(u, g_W2048[j]);                    // stage twiddle (tmul=1)
#pragma unroll
        for (int k = 0; k < 8; k++) sm[row][SW(j + (k << 8))] = u[k];
    }
    __syncthreads();

    // remaining forward DIF radix-8 stages
    k3_r8(sm, nrow, t, 5, 8,  0);   // sub-len 256,  span 32
    k3_r8(sm, nrow, t, 2, 64, 0);   // sub-len 32,   span 4

    if (idx == 0) {
        // h == 0: unfused path (partner f2 = (FA - f1) mod FA)
        k3_r4(sm, nrow, t, 1.f);
        for (int a1 = t; a1 <= FA / 2; a1 += NTHR) {
            if (a1 == 0 || a1 == FA / 2) {
                int p = pos2048(a1);
                float2 z = sm[0][SW(p)];
                sm[0][SW(p)] = make_float2(z.x * z.y, 0.f);   // DU=Re(z), B=Im(z)
            } else {
                int p1 = pos2048(a1), p2 = pos2048(FA - a1);
                float2 z1 = sm[0][SW(p1)];
                float2 z2 = sm[0][SW(p2)];
                float2 P  = herm_P(z1, z2);
                sm[0][SW(p1)] = P;
                sm[0][SW(p2)] = make_float2(P.x, -P.y);
            }
        }
        __syncthreads();
        k3_r4(sm, nrow, t, -1.f);
    } else {
        // fused middle: r4 fwd + Hermitian pairing + r4 inv, one register pass
        const int ntask = self ? 256 : 512;
        for (int w = t; w < ntask; w += NTHR) {
            float2* rA = sm[0];
            float2* rB = self ? sm[0] : sm[1];
            const int ba = w << 2;
            const int bb = (511 - w) << 2;
            float4 alo = *reinterpret_cast<const float4*>(&rA[SW(ba)]);
            float4 ahi = *reinterpret_cast<const float4*>(&rA[SW(ba + 2)]);
            float4 blo = *reinterpret_cast<const float4*>(&rB[SW(bb)]);
            float4 bhi = *reinterpret_cast<const float4*>(&rB[SW(bb + 2)]);
            float2 uA[4] = { make_float2(alo.x, alo.y), make_float2(alo.z, alo.w),
                             make_float2(ahi.x, ahi.y), make_float2(ahi.z, ahi.w) };
            float2 uB[4] = { make_float2(blo.x, blo.y), make_float2(blo.z, blo.w),
                             make_float2(bhi.x, bhi.y), make_float2(bhi.z, bhi.w) };
            dft4(uA, 1.f); dft4(uB, 1.f);
#pragma unroll
            for (int e = 0; e < 4; e++) {
                // partner of position ba+e is bb+(3-e) (= 2047 - (ba+e))
                float2 P = herm_P(uA[e], uB[3 - e]);
                uA[e]     = P;
                uB[3 - e] = make_float2(P.x, -P.y);
            }
            dft4(uA, -1.f);
            *reinterpret_cast<float4*>(&rA[SW(ba)])     = make_float4(uA[0].x, uA[0].y, uA[1].x, uA[1].y);
            *reinterpret_cast<float4*>(&rA[SW(ba + 2)]) = make_float4(uA[2].x, uA[2].y, uA[3].x, uA[3].y);
            if (self || keep1) {               // row1 (rB) consumed downstream?
                dft4(uB, -1.f);
                *reinterpret_cast<float4*>(&rB[SW(bb)])     = make_float4(uB[0].x, uB[0].y, uB[1].x, uB[1].y);
                *reinterpret_cast<float4*>(&rB[SW(bb + 2)]) = make_float4(uB[2].x, uB[2].y, uB[3].x, uB[3].y);
            }
        }
        __syncthreads();
    }

    // inverse DIT radix-8 stages (mirror order, conj twiddles), live rows only
    k3_r8(sm, nrow_inv, t, 2, 64, 1);
    k3_r8(sm, nrow_inv, t, 5, 8,  1);

    // FUSED last inverse stage (span 256) + post-twiddle conj(W_N^{a*hk}) + STG.
    for (int q = t; q < (nrow_inv << 8); q += NTHR) {
        int row = q >> 8, j = q & 255;
        const int chunk = row ? h2 : h1;
        const int hk    = row ? hk2 : hk1;
        float2 u[8];
#pragma unroll
        for (int k = 0; k < 8; k++) u[k] = sm[row][SW(j + (k << 8))];
        float2 w1 = g_W2048[j]; w1.y = -w1.y;             // conj stage twiddle
        twiddle_chain8(u, w1);
        dft8(u, -1.f);
#pragma unroll
        for (int k = 0; k < 8; k++) {
            int a = j + (k << 8);
            int e = a * hk;
            float2 w = cmul(g_Whi[e >> 12], g_Wlo[e & 4095]);
            w.y = -w.y;
            g_Z[chunk * FA + a] = cmul(u[k], w);
        }
    }
}

// -------- K5: inverse FFT over c' with stage-2 fused into the physics epilogue.
// Stage 1: PREFETCH all 16 global loads (mirror-conj for rows > 64), then two
// inverse butterflies. Only even positions p (c = f128(p) < 64) are needed.
__global__ __launch_bounds__(NTHR)
void k5_inv_epi(const float* __restrict__ up, float coefN) {
    __shared__ float2 tile[FC][GT + 1];
    __shared__ double red[NTHR];
    const int t   = threadIdx.x;
    const int ab0 = blockIdx.x * GT;
    const int g   = t & 31;
    const int j0  = t >> 5;                    // [0,8), second half j0+8

    // stage 1: prefetch 16 (with mirror conj), then two butterflies
    {
        float2 v0[8], v1[8];
#pragma unroll
        for (int k = 0; k < 8; k++) {
            int row = j0 + (k << 4);
            int src = (row <= 64) ? row : (128 - row);
            v0[k] = g_Z[ab0 + g + AB * src];
            if (row > 64) v0[k].y = -v0[k].y;
        }
#pragma unroll
        for (int k = 0; k < 8; k++) {
            int row = j0 + 8 + (k << 4);
            int src = (row <= 64) ? row : (128 - row);
            v1[k] = g_Z[ab0 + g + AB * src];
            if (row > 64) v1[k].y = -v1[k].y;
        }

        dft8(v0, -1.f);
        { float2 w1 = g_W128[j0]; w1.y = -w1.y; twiddle_chain8(v0, w1); }
#pragma unroll
        for (int k = 0; k < 8; k++) tile[j0 + (k << 4)][g] = v0[k];

        dft8(v1, -1.f);
        { float2 w1 = g_W128[j0 + 8]; w1.y = -w1.y; twiddle_chain8(v1, w1); }
#pragma unroll
        for (int k = 0; k < 8; k++) tile[j0 + 8 + (k << 4)][g] = v1[k];
    }
    __syncthreads();

    // fused stage 2 (even outputs only) + epilogue
    float acc = 0.f;
    {
        int m = t >> 5;                        // m in [0,8)
        int base = m << 4;
        float2 e0[8], e1[8];
#pragma unroll
        for (int k = 0; k < 8; k++) {
            e0[k] = tile[base + (k << 1)][g];
            e1[k] = tile[base + (k << 1) + 1][g];
        }
        dft8(e0, -1.f); dft8(e1, -1.f);
#pragma unroll
        for (int k = 1; k < 8; k++) {
            float2 w = g_W128[k << 3]; w.y = -w.y;   // conj W16^k
            e1[k] = cmul(e1[k], w);
        }
#pragma unroll
        for (int k = 0; k < 8; k++) {
            float convr = e0[k].x + e1[k].x;          // even output, real part
            int c = m + (k << 3);                     // f128(16m + 2k) = m + 8k  (< 64)
            int n = ab0 + g + AB * c;                 // conv index
            int mres = n + 1;                         // frac[mres] = coef*conv[mres-1]
            if (mres < MTOT) {
                float um = __ldg(up + mres);
                float ut = 0.f;
                if ((mres & 16383) != 16383) ut = __ldg(up + mres + 1) - um;  // last col: u_t=0
                float r = ut - coefN * convr;
                acc = fmaf(r, r, acc);
            }
        }
    }

    red[t] = (double)acc;
    __syncthreads();
    for (int s = NTHR / 2; s > 0; s >>= 1) { if (t < s) red[t] += red[t + s]; __syncthreads(); }
    if (t == 0) g_phys[blockIdx.x] = red[0];
}

// -------- finalize
__global__ void k_fin(const float* __restrict__ up, float* __restrict__ out) {
    __shared__ double rp[256], rd[256];
    int t = threadIdx.x;
    double sp = 0.0, sd = 0.0;
    for (int i = t; i < NBLK; i += 256) { sp += g_phys[i]; sd += g_data[i]; }
    rp[t] = sp; rd[t] = sd;
    __syncthreads();
    for (int s = 128; s > 0; s >>= 1) {
        if (t < s) { rp[t] += rp[t + s]; rd[t] += rd[t + s]; }
        __syncthreads();
    }
    if (t == 0) {
        double r0 = (double)up[1] - (double)up[0];    // m = 0 residual: u_t[0] - 0
        double phys = (rp[0] + r0 * r0) / (double)MTOT;
        double data = rd[0] / (double)MTOT;
        out[0] = (float)(data + 0.1 * phys);
        out[1] = (float)data;
        out[2] = (float)phys;
    }
}

extern "C" void kernel_launch(void* const* d_in, const int* in_sizes, int n_in,
                              void* d_out, int out_size)
{
    const float* up  = (const float*)d_in[0];  // u_pred
    const float* utr = (const float*)d_in[1];  // u_true
    (void)in_sizes; (void)n_in; (void)out_size;

    // coef = sqrt(M-1)/Gamma(1.5); fold the 1/N of the fwd+inv FFT product in here.
    double coefN = sqrt((double)(MTOT - 1)) / 0.886226925452758013649083741670572
                   / (double)NF;

    k_tw<<<128, 128>>>();
    k1_pack_fft<<<NBLK, NTHR>>>(up, utr);
    k2_fftb<1><<<NBLK, NTHR>>>();
    k3_core<<<8193, NTHR>>>();
    k2_fftb<0><<<65 * 64, NTHR>>>();           // only c' <= 64 needed (Hermitian)
    k5_inv_epi<<<NBLK, NTHR>>>(up, (float)coefN);
    k_fin<<<1, 256>>>(up, (float*)d_out);
}